// round 1
// baseline (speedup 1.0000x reference)
#include <cuda_runtime.h>

#define NNODES 20000
#define NEDGES 320000
#define FNODE  64
#define FEDGE  16
#define HIDN   300
#define NGRAPH 128

typedef unsigned long long ull;

// ---------------- scratch (device globals: allocation-free rule) ----------------
__device__ float g_h0[NEDGES * HIDN];     // 384 MB
__device__ float g_hA[NEDGES * HIDN];     // 384 MB
__device__ float g_hB[NEDGES * HIDN];     // 384 MB
__device__ float g_a [NNODES * HIDN];     // 24 MB  (segment sums / s)
__device__ float g_pool[NGRAPH * HIDN];   // pooled
__device__ int   g_cnt [NNODES];
__device__ int   g_ptr [NNODES + 1];
__device__ int   g_fill[NNODES];
__device__ int   g_eid [NEDGES];

__device__ __forceinline__ float* hbuf(int s) {
    return (s == 0) ? g_h0 : ((s == 1) ? g_hA : g_hB);
}

// ---------------- small helpers ----------------
__device__ __forceinline__ float4 ld4(const float* p) { return *reinterpret_cast<const float4*>(p); }
__device__ __forceinline__ void   st4(float* p, float4 v) { *reinterpret_cast<float4*>(p) = v; }
__device__ __forceinline__ float  frelu(float x) { return x > 0.f ? x : 0.f; }

__device__ __forceinline__ ull fma2(ull a, ull b, ull c) {
    ull d;
    asm("fma.rn.f32x2 %0, %1, %2, %3;" : "=l"(d) : "l"(a), "l"(b), "l"(c));
    return d;
}
__device__ __forceinline__ void unpack2(ull v, float& lo, float& hi) {
    asm("mov.b64 {%0, %1}, %2;" : "=f"(lo), "=f"(hi) : "l"(v));
}

// ---------------- CSR build ----------------
__global__ void k_zero_cnt() {
    int i = blockIdx.x * blockDim.x + threadIdx.x;
    if (i < NNODES) g_cnt[i] = 0;
}

__global__ void k_hist(const int* __restrict__ coli) {
    int e = blockIdx.x * blockDim.x + threadIdx.x;
    if (e < NEDGES) atomicAdd(&g_cnt[coli[e]], 1);
}

__global__ void k_scan() {
    __shared__ int sh[1024];
    int tid = threadIdx.x;
    int carry = 0;
    const int CH = (NNODES + 1023) / 1024;  // 20
    for (int c = 0; c < CH; ++c) {
        int i = c * 1024 + tid;
        int v = (i < NNODES) ? g_cnt[i] : 0;
        sh[tid] = v;
        __syncthreads();
        for (int off = 1; off < 1024; off <<= 1) {
            int t = (tid >= off) ? sh[tid - off] : 0;
            __syncthreads();
            sh[tid] += t;
            __syncthreads();
        }
        int inc = sh[tid];
        int total = sh[1023];
        if (i < NNODES) {
            int ex = carry + inc - v;
            g_ptr[i]  = ex;
            g_fill[i] = ex;
        }
        carry += total;
        __syncthreads();
    }
    if (tid == 0) g_ptr[NNODES] = carry;
}

__global__ void k_scatter(const int* __restrict__ coli) {
    int e = blockIdx.x * blockDim.x + threadIdx.x;
    if (e < NEDGES) {
        int pos = atomicAdd(&g_fill[coli[e]], 1);
        g_eid[pos] = e;
    }
}

// ---------------- segment sum: a[n] = sum_{e: col[e]==n} h[e] ----------------
__global__ void k_segsum(int in_sel) {
    const float* h = hbuf(in_sel);
    int t = blockIdx.x * blockDim.x + threadIdx.x;
    if (t >= NNODES * 75) return;
    int n = t / 75;
    int c = (t - n * 75) * 4;
    int beg = g_ptr[n], end = g_ptr[n + 1];
    float4 acc = make_float4(0.f, 0.f, 0.f, 0.f);
    for (int i = beg; i < end; ++i) {
        int e = g_eid[i];
        float4 vv = ld4(h + e * HIDN + c);
        acc.x += vv.x; acc.y += vv.y; acc.z += vv.z; acc.w += vv.w;
    }
    st4(g_a + n * HIDN + c, acc);
}

// ---------------- init GEMM: h0 = relu([x[row]|edge_attr] @ W_init + b) ----------------
// BM=128 edges, BN=64 cols (5 n-tiles cover 300 padded to 320), BK=20, 256 threads.
__global__ __launch_bounds__(256, 2) void k_init(
    const float* __restrict__ x, const float* __restrict__ ea,
    const int* __restrict__ rowi,
    const float* __restrict__ W, const float* __restrict__ bias)
{
    __shared__ float As[20 * 128];
    __shared__ float Bs[20 * 128];
    int tid = threadIdx.x;
    int m0 = blockIdx.y * 128;
    int n0 = blockIdx.x * 64;
    int r  = tid & 127;
    int v0 = tid >> 7;
    int eg = m0 + r;
    int xbase = rowi[eg] * FNODE;
    int ty = tid >> 4, tx = tid & 15;

    ull acc[4][4];
#pragma unroll
    for (int i = 0; i < 4; i++)
#pragma unroll
        for (int j = 0; j < 4; j++) acc[i][j] = 0ull;

    float4 pa[3], pb[2];
    const int NK = 4;  // K = 80

#define INIT_LOAD(K0)                                                              \
    {                                                                              \
        int k0 = (K0);                                                             \
        _Pragma("unroll")                                                          \
        for (int s = 0; s < 3; s++) {                                              \
            int v = v0 + 2 * s;                                                    \
            if (v < 5) {                                                           \
                int k = k0 + v * 4;                                                \
                pa[s] = (k < FNODE) ? ld4(x + xbase + k)                           \
                                    : ld4(ea + eg * FEDGE + (k - FNODE));          \
            }                                                                      \
        }                                                                          \
        _Pragma("unroll")                                                          \
        for (int s = 0; s < 2; s++) {                                              \
            int j = tid + s * 256;                                                 \
            if (j < 320) {                                                         \
                int kk = j >> 4, nv = j & 15;                                      \
                int n = n0 + nv * 4;                                               \
                pb[s] = (n < HIDN) ? ld4(W + (k0 + kk) * HIDN + n)                 \
                                   : make_float4(0.f, 0.f, 0.f, 0.f);              \
            }                                                                      \
        }                                                                          \
    }

    INIT_LOAD(0)
    for (int ks = 0; ks < NK; ++ks) {
        __syncthreads();
#pragma unroll
        for (int s = 0; s < 3; s++) {
            int v = v0 + 2 * s;
            if (v < 5) {
                As[(v * 4 + 0) * 128 + r] = pa[s].x;
                As[(v * 4 + 1) * 128 + r] = pa[s].y;
                As[(v * 4 + 2) * 128 + r] = pa[s].z;
                As[(v * 4 + 3) * 128 + r] = pa[s].w;
            }
        }
#pragma unroll
        for (int s = 0; s < 2; s++) {
            int j = tid + s * 256;
            if (j < 320) {
                int kk = j >> 4, nv = j & 15;
                float4 w = pb[s];
                st4(&Bs[kk * 128 + nv * 8],     make_float4(w.x, w.x, w.y, w.y));
                st4(&Bs[kk * 128 + nv * 8 + 4], make_float4(w.z, w.z, w.w, w.w));
            }
        }
        __syncthreads();
        if (ks + 1 < NK) INIT_LOAD((ks + 1) * 20)
#pragma unroll
        for (int kk = 0; kk < 20; kk++) {
            ulonglong2 ta0 = *reinterpret_cast<const ulonglong2*>(&As[kk * 128 + ty * 8]);
            ulonglong2 ta1 = *reinterpret_cast<const ulonglong2*>(&As[kk * 128 + ty * 8 + 4]);
            ulonglong2 tb0 = *reinterpret_cast<const ulonglong2*>(&Bs[kk * 128 + tx * 8]);
            ulonglong2 tb1 = *reinterpret_cast<const ulonglong2*>(&Bs[kk * 128 + tx * 8 + 4]);
            ull a2[4] = {ta0.x, ta0.y, ta1.x, ta1.y};
            ull b2[4] = {tb0.x, tb0.y, tb1.x, tb1.y};
#pragma unroll
            for (int i = 0; i < 4; i++)
#pragma unroll
                for (int j = 0; j < 4; j++) acc[i][j] = fma2(a2[i], b2[j], acc[i][j]);
        }
    }
    int n = n0 + tx * 4;
    if (n < HIDN) {
        float4 b4 = ld4(bias + n);
#pragma unroll
        for (int i = 0; i < 4; i++) {
            int m = m0 + ty * 8 + 2 * i;
            float lo0, hi0, lo1, hi1, lo2, hi2, lo3, hi3;
            unpack2(acc[i][0], lo0, hi0); unpack2(acc[i][1], lo1, hi1);
            unpack2(acc[i][2], lo2, hi2); unpack2(acc[i][3], lo3, hi3);
            float4 o0 = make_float4(frelu(lo0 + b4.x), frelu(lo1 + b4.y),
                                    frelu(lo2 + b4.z), frelu(lo3 + b4.w));
            float4 o1 = make_float4(frelu(hi0 + b4.x), frelu(hi1 + b4.y),
                                    frelu(hi2 + b4.z), frelu(hi3 + b4.w));
            st4(g_h0 + m * HIDN + n, o0);
            st4(g_h0 + (m + 1) * HIDN + n, o1);
        }
    }
#undef INIT_LOAD
}

// ---------------- conv GEMM: h_out = relu((a[row]-h[e^1]) @ W + b + h0) ----------------
__global__ __launch_bounds__(256, 2) void k_conv(
    int in_sel, int out_sel,
    const int* __restrict__ rowi,
    const float* __restrict__ W, const float* __restrict__ bias)
{
    const float* h_in  = hbuf(in_sel);
    float*       h_out = hbuf(out_sel);
    __shared__ float As[20 * 128];
    __shared__ float Bs[20 * 128];
    int tid = threadIdx.x;
    int m0 = blockIdx.y * 128;
    int n0 = blockIdx.x * 64;
    int r  = tid & 127;
    int v0 = tid >> 7;
    int eg = m0 + r;
    int abase = rowi[eg] * HIDN;
    int hbase = (eg ^ 1) * HIDN;
    int ty = tid >> 4, tx = tid & 15;

    ull acc[4][4];
#pragma unroll
    for (int i = 0; i < 4; i++)
#pragma unroll
        for (int j = 0; j < 4; j++) acc[i][j] = 0ull;

    float4 pa[3], pb[2];
    const int NK = 15;  // K = 300

#define CONV_LOAD(K0)                                                              \
    {                                                                              \
        int k0 = (K0);                                                             \
        _Pragma("unroll")                                                          \
        for (int s = 0; s < 3; s++) {                                              \
            int v = v0 + 2 * s;                                                    \
            if (v < 5) {                                                           \
                int k = k0 + v * 4;                                                \
                float4 a4 = ld4(g_a + abase + k);                                  \
                float4 h4 = ld4(h_in + hbase + k);                                 \
                pa[s] = make_float4(a4.x - h4.x, a4.y - h4.y,                      \
                                    a4.z - h4.z, a4.w - h4.w);                     \
            }                                                                      \
        }                                                                          \
        _Pragma("unroll")                                                          \
        for (int s = 0; s < 2; s++) {                                              \
            int j = tid + s * 256;                                                 \
            if (j < 320) {                                                         \
                int kk = j >> 4, nv = j & 15;                                      \
                int n = n0 + nv * 4;                                               \
                pb[s] = (n < HIDN) ? ld4(W + (k0 + kk) * HIDN + n)                 \
                                   : make_float4(0.f, 0.f, 0.f, 0.f);              \
            }                                                                      \
        }                                                                          \
    }

    CONV_LOAD(0)
    for (int ks = 0; ks < NK; ++ks) {
        __syncthreads();
#pragma unroll
        for (int s = 0; s < 3; s++) {
            int v = v0 + 2 * s;
            if (v < 5) {
                As[(v * 4 + 0) * 128 + r] = pa[s].x;
                As[(v * 4 + 1) * 128 + r] = pa[s].y;
                As[(v * 4 + 2) * 128 + r] = pa[s].z;
                As[(v * 4 + 3) * 128 + r] = pa[s].w;
            }
        }
#pragma unroll
        for (int s = 0; s < 2; s++) {
            int j = tid + s * 256;
            if (j < 320) {
                int kk = j >> 4, nv = j & 15;
                float4 w = pb[s];
                st4(&Bs[kk * 128 + nv * 8],     make_float4(w.x, w.x, w.y, w.y));
                st4(&Bs[kk * 128 + nv * 8 + 4], make_float4(w.z, w.z, w.w, w.w));
            }
        }
        __syncthreads();
        if (ks + 1 < NK) CONV_LOAD((ks + 1) * 20)
#pragma unroll
        for (int kk = 0; kk < 20; kk++) {
            ulonglong2 ta0 = *reinterpret_cast<const ulonglong2*>(&As[kk * 128 + ty * 8]);
            ulonglong2 ta1 = *reinterpret_cast<const ulonglong2*>(&As[kk * 128 + ty * 8 + 4]);
            ulonglong2 tb0 = *reinterpret_cast<const ulonglong2*>(&Bs[kk * 128 + tx * 8]);
            ulonglong2 tb1 = *reinterpret_cast<const ulonglong2*>(&Bs[kk * 128 + tx * 8 + 4]);
            ull a2[4] = {ta0.x, ta0.y, ta1.x, ta1.y};
            ull b2[4] = {tb0.x, tb0.y, tb1.x, tb1.y};
#pragma unroll
            for (int i = 0; i < 4; i++)
#pragma unroll
                for (int j = 0; j < 4; j++) acc[i][j] = fma2(a2[i], b2[j], acc[i][j]);
        }
    }
    int n = n0 + tx * 4;
    if (n < HIDN) {
        float4 b4 = ld4(bias + n);
#pragma unroll
        for (int i = 0; i < 4; i++) {
            int m = m0 + ty * 8 + 2 * i;
            float lo0, hi0, lo1, hi1, lo2, hi2, lo3, hi3;
            unpack2(acc[i][0], lo0, hi0); unpack2(acc[i][1], lo1, hi1);
            unpack2(acc[i][2], lo2, hi2); unpack2(acc[i][3], lo3, hi3);
            float4 h0a = ld4(g_h0 + m * HIDN + n);
            float4 h0b = ld4(g_h0 + (m + 1) * HIDN + n);
            float4 o0 = make_float4(frelu(lo0 + b4.x + h0a.x), frelu(lo1 + b4.y + h0a.y),
                                    frelu(lo2 + b4.z + h0a.z), frelu(lo3 + b4.w + h0a.w));
            float4 o1 = make_float4(frelu(hi0 + b4.x + h0b.x), frelu(hi1 + b4.y + h0b.y),
                                    frelu(hi2 + b4.z + h0b.z), frelu(hi3 + b4.w + h0b.w));
            st4(h_out + m * HIDN + n, o0);
            st4(h_out + (m + 1) * HIDN + n, o1);
        }
    }
#undef CONV_LOAD
}

// ---------------- node GEMM: hn = relu([x|s] @ W_e2n + b); pooled += hn ----------------
__global__ __launch_bounds__(256, 2) void k_node(
    const float* __restrict__ x, const int* __restrict__ batch,
    const float* __restrict__ W, const float* __restrict__ bias)
{
    __shared__ float As[20 * 128];
    __shared__ float Bs[20 * 128];
    int tid = threadIdx.x;
    int m0 = blockIdx.y * 128;
    int n0 = blockIdx.x * 64;
    int r  = tid & 127;
    int v0 = tid >> 7;
    int eg = m0 + r;
    bool mok = (eg < NNODES);
    int xbase = (mok ? eg : 0) * FNODE;
    int sbase = (mok ? eg : 0) * HIDN;
    int ty = tid >> 4, tx = tid & 15;
    const int KTOT = FNODE + HIDN;  // 364

    ull acc[4][4];
#pragma unroll
    for (int i = 0; i < 4; i++)
#pragma unroll
        for (int j = 0; j < 4; j++) acc[i][j] = 0ull;

    float4 pa[3], pb[2];
    const int NK = 19;  // ceil(364/20)

#define NODE_LOAD(K0)                                                              \
    {                                                                              \
        int k0 = (K0);                                                             \
        _Pragma("unroll")                                                          \
        for (int s = 0; s < 3; s++) {                                              \
            int v = v0 + 2 * s;                                                    \
            if (v < 5) {                                                           \
                int k = k0 + v * 4;                                                \
                if (mok && k < KTOT)                                               \
                    pa[s] = (k < FNODE) ? ld4(x + xbase + k)                       \
                                        : ld4(g_a + sbase + (k - FNODE));          \
                else                                                               \
                    pa[s] = make_float4(0.f, 0.f, 0.f, 0.f);                       \
            }                                                                      \
        }                                                                          \
        _Pragma("unroll")                                                          \
        for (int s = 0; s < 2; s++) {                                              \
            int j = tid + s * 256;                                                 \
            if (j < 320) {                                                         \
                int kk = j >> 4, nv = j & 15;                                      \
                int k = k0 + kk;                                                   \
                int n = n0 + nv * 4;                                               \
                pb[s] = (k < KTOT && n < HIDN) ? ld4(W + k * HIDN + n)             \
                                               : make_float4(0.f, 0.f, 0.f, 0.f);  \
            }                                                                      \
        }                                                                          \
    }

    NODE_LOAD(0)
    for (int ks = 0; ks < NK; ++ks) {
        __syncthreads();
#pragma unroll
        for (int s = 0; s < 3; s++) {
            int v = v0 + 2 * s;
            if (v < 5) {
                As[(v * 4 + 0) * 128 + r] = pa[s].x;
                As[(v * 4 + 1) * 128 + r] = pa[s].y;
                As[(v * 4 + 2) * 128 + r] = pa[s].z;
                As[(v * 4 + 3) * 128 + r] = pa[s].w;
            }
        }
#pragma unroll
        for (int s = 0; s < 2; s++) {
            int j = tid + s * 256;
            if (j < 320) {
                int kk = j >> 4, nv = j & 15;
                float4 w = pb[s];
                st4(&Bs[kk * 128 + nv * 8],     make_float4(w.x, w.x, w.y, w.y));
                st4(&Bs[kk * 128 + nv * 8 + 4], make_float4(w.z, w.z, w.w, w.w));
            }
        }
        __syncthreads();
        if (ks + 1 < NK) NODE_LOAD((ks + 1) * 20)
#pragma unroll
        for (int kk = 0; kk < 20; kk++) {
            ulonglong2 ta0 = *reinterpret_cast<const ulonglong2*>(&As[kk * 128 + ty * 8]);
            ulonglong2 ta1 = *reinterpret_cast<const ulonglong2*>(&As[kk * 128 + ty * 8 + 4]);
            ulonglong2 tb0 = *reinterpret_cast<const ulonglong2*>(&Bs[kk * 128 + tx * 8]);
            ulonglong2 tb1 = *reinterpret_cast<const ulonglong2*>(&Bs[kk * 128 + tx * 8 + 4]);
            ull a2[4] = {ta0.x, ta0.y, ta1.x, ta1.y};
            ull b2[4] = {tb0.x, tb0.y, tb1.x, tb1.y};
#pragma unroll
            for (int i = 0; i < 4; i++)
#pragma unroll
                for (int j = 0; j < 4; j++) acc[i][j] = fma2(a2[i], b2[j], acc[i][j]);
        }
    }
    int n = n0 + tx * 4;
    if (n < HIDN) {
        float4 b4 = ld4(bias + n);
#pragma unroll
        for (int i = 0; i < 4; i++) {
            int m = m0 + ty * 8 + 2 * i;
            float lo0, hi0, lo1, hi1, lo2, hi2, lo3, hi3;
            unpack2(acc[i][0], lo0, hi0); unpack2(acc[i][1], lo1, hi1);
            unpack2(acc[i][2], lo2, hi2); unpack2(acc[i][3], lo3, hi3);
            if (m < NNODES) {
                int bg = batch[m];
                float* p = g_pool + bg * HIDN + n;
                atomicAdd(p + 0, frelu(lo0 + b4.x));
                atomicAdd(p + 1, frelu(lo1 + b4.y));
                atomicAdd(p + 2, frelu(lo2 + b4.z));
                atomicAdd(p + 3, frelu(lo3 + b4.w));
            }
            if (m + 1 < NNODES) {
                int bg = batch[m + 1];
                float* p = g_pool + bg * HIDN + n;
                atomicAdd(p + 0, frelu(hi0 + b4.x));
                atomicAdd(p + 1, frelu(hi1 + b4.y));
                atomicAdd(p + 2, frelu(hi2 + b4.z));
                atomicAdd(p + 3, frelu(hi3 + b4.w));
            }
        }
    }
#undef NODE_LOAD
}

// ---------------- misc ----------------
__global__ void k_zero_pool() {
    int i = blockIdx.x * blockDim.x + threadIdx.x;
    if (i < NGRAPH * HIDN) g_pool[i] = 0.f;
}

__global__ void k_ffn(const float* __restrict__ Wf, const float* __restrict__ bf,
                      float* __restrict__ out) {
    int g = blockIdx.x;
    int lane = threadIdx.x;
    float s = 0.f;
    for (int k = lane; k < HIDN; k += 32) s += g_pool[g * HIDN + k] * Wf[k];
#pragma unroll
    for (int o = 16; o; o >>= 1) s += __shfl_xor_sync(0xffffffffu, s, o);
    if (lane == 0) out[g] = s + bf[0];
}

// ---------------- entry ----------------
extern "C" void kernel_launch(void* const* d_in, const int* in_sizes, int n_in,
                              void* d_out, int out_size) {
    const float* x     = (const float*)d_in[0];
    const float* ea    = (const float*)d_in[1];
    const int*   ei    = (const int*)d_in[2];
    const int*   rowi  = ei;
    const int*   coli  = ei + NEDGES;
    const int*   batch = (const int*)d_in[3];
    const float* Wi    = (const float*)d_in[4];
    const float* bi    = (const float*)d_in[5];
    const float* Wc    = (const float*)d_in[6];
    const float* bc    = (const float*)d_in[7];
    const float* We    = (const float*)d_in[8];
    const float* be    = (const float*)d_in[9];
    const float* Wf    = (const float*)d_in[10];
    const float* bf    = (const float*)d_in[11];
    float* out = (float*)d_out;

    // CSR build (by col)
    k_zero_cnt<<<(NNODES + 255) / 256, 256>>>();
    k_hist<<<NEDGES / 256, 256>>>(coli);
    k_scan<<<1, 1024>>>();
    k_scatter<<<NEDGES / 256, 256>>>(coli);

    dim3 gE(5, NEDGES / 128);  // 5 x 2500
    k_init<<<gE, 256>>>(x, ea, rowi, Wi, bi);

    int cur = 0;  // g_h0
    for (int l = 0; l < 3; ++l) {
        k_segsum<<<(NNODES * 75 + 255) / 256, 256>>>(cur);
        int nxt = (cur == 1) ? 2 : 1;
        k_conv<<<gE, 256>>>(cur, nxt, rowi, Wc + l * HIDN * HIDN, bc + l * HIDN);
        cur = nxt;
    }

    k_segsum<<<(NNODES * 75 + 255) / 256, 256>>>(cur);
    k_zero_pool<<<(NGRAPH * HIDN + 255) / 256, 256>>>();
    dim3 gN(5, (NNODES + 127) / 128);
    k_node<<<gN, 256>>>(x, batch, We, be);
    k_ffn<<<NGRAPH, 32>>>(Wf, bf, out);
}

// round 2
// speedup vs baseline: 1.2938x; 1.2938x over previous
#include <cuda_runtime.h>

#define NNODES 20000
#define NEDGES 320000
#define FNODE  64
#define FEDGE  16
#define HIDN   300
#define NGRAPH 128

typedef unsigned long long ull;

// ---------------- scratch (device globals: allocation-free rule) ----------------
__device__ float g_h0[NEDGES * HIDN];
__device__ float g_hA[NEDGES * HIDN];
__device__ float g_hB[NEDGES * HIDN];
__device__ float g_a [NNODES * HIDN];
__device__ float g_pool[NGRAPH * HIDN];
__device__ int   g_cnt [NNODES];
__device__ int   g_ptr [NNODES + 1];
__device__ int   g_fill[NNODES];
__device__ int   g_eid [NEDGES];

__device__ __forceinline__ float* hbuf(int s) {
    return (s == 0) ? g_h0 : ((s == 1) ? g_hA : g_hB);
}

// ---------------- small helpers ----------------
__device__ __forceinline__ float4 ld4(const float* p) { return *reinterpret_cast<const float4*>(p); }
__device__ __forceinline__ void   st4(float* p, float4 v) { *reinterpret_cast<float4*>(p) = v; }
__device__ __forceinline__ float  frelu(float x) { return x > 0.f ? x : 0.f; }

__device__ __forceinline__ ull fma2(ull a, ull b, ull c) {
    ull d;
    asm("fma.rn.f32x2 %0, %1, %2, %3;" : "=l"(d) : "l"(a), "l"(b), "l"(c));
    return d;
}
__device__ __forceinline__ void unpack2(ull v, float& lo, float& hi) {
    asm("mov.b64 {%0, %1}, %2;" : "=f"(lo), "=f"(hi) : "l"(v));
}

// ---------------- CSR build ----------------
__global__ void k_zero() {
    int i = blockIdx.x * blockDim.x + threadIdx.x;
    if (i < NNODES) g_cnt[i] = 0;
    if (i < NGRAPH * HIDN) g_pool[i] = 0.f;
}

__global__ void k_hist(const int* __restrict__ coli) {
    int e = blockIdx.x * blockDim.x + threadIdx.x;
    if (e < NEDGES) atomicAdd(&g_cnt[coli[e]], 1);
}

__global__ void k_scan() {
    __shared__ int sh[1024];
    int tid = threadIdx.x;
    int carry = 0;
    const int CH = (NNODES + 1023) / 1024;
    for (int c = 0; c < CH; ++c) {
        int i = c * 1024 + tid;
        int v = (i < NNODES) ? g_cnt[i] : 0;
        sh[tid] = v;
        __syncthreads();
        for (int off = 1; off < 1024; off <<= 1) {
            int t = (tid >= off) ? sh[tid - off] : 0;
            __syncthreads();
            sh[tid] += t;
            __syncthreads();
        }
        int inc = sh[tid];
        int total = sh[1023];
        if (i < NNODES) {
            int ex = carry + inc - v;
            g_ptr[i]  = ex;
            g_fill[i] = ex;
        }
        carry += total;
        __syncthreads();
    }
    if (tid == 0) g_ptr[NNODES] = carry;
}

__global__ void k_scatter(const int* __restrict__ coli) {
    int e = blockIdx.x * blockDim.x + threadIdx.x;
    if (e < NEDGES) {
        int pos = atomicAdd(&g_fill[coli[e]], 1);
        g_eid[pos] = e;
    }
}

// ---------------- segment sum: a[n] = sum_{e: col[e]==n} h[e] ----------------
__global__ void k_segsum(int in_sel) {
    const float* h = hbuf(in_sel);
    int t = blockIdx.x * blockDim.x + threadIdx.x;
    if (t >= NNODES * 75) return;
    int n = t / 75;
    int c = (t - n * 75) * 4;
    int beg = g_ptr[n], end = g_ptr[n + 1];
    float4 acc = make_float4(0.f, 0.f, 0.f, 0.f);
    for (int i = beg; i < end; ++i) {
        int e = g_eid[i];
        float4 vv = ld4(h + e * HIDN + c);
        acc.x += vv.x; acc.y += vv.y; acc.z += vv.z; acc.w += vv.w;
    }
    st4(g_a + n * HIDN + c, acc);
}

// =====================================================================
// GEMM core: 128m x 64n block tile, 128 threads, 8m x 8n per thread.
// A stored DUPLICATED in smem (each value twice -> f32x2 pairs come free).
// B stored naturally; acc packs (n, n+1) column pairs.
// ty = tid>>3 (16 values * 8m), tx = tid&7 (8 values * 8n).
// =====================================================================

#define GEMM_DECLS                                                         \
    __shared__ __align__(16) float As[20 * 256];                           \
    __shared__ __align__(16) float Bs[20 * 64];                            \
    float2* As2 = reinterpret_cast<float2*>(As);                           \
    int tid = threadIdx.x;                                                 \
    int ty = tid >> 3, tx = tid & 7;                                       \
    ull acc[8][4];                                                         \
    _Pragma("unroll")                                                      \
    for (int i = 0; i < 8; i++)                                            \
        _Pragma("unroll")                                                  \
        for (int j = 0; j < 4; j++) acc[i][j] = 0ull;                      \
    float4 pa[5], pb[3];

#define GEMM_STORE_STAGE                                                   \
    _Pragma("unroll")                                                      \
    for (int v = 0; v < 5; v++) {                                          \
        float4 w = pa[v];                                                  \
        As2[(v * 4 + 0) * 128 + tid] = make_float2(w.x, w.x);              \
        As2[(v * 4 + 1) * 128 + tid] = make_float2(w.y, w.y);              \
        As2[(v * 4 + 2) * 128 + tid] = make_float2(w.z, w.z);              \
        As2[(v * 4 + 3) * 128 + tid] = make_float2(w.w, w.w);              \
    }                                                                      \
    _Pragma("unroll")                                                      \
    for (int s = 0; s < 3; s++) {                                          \
        int j = tid + s * 128;                                             \
        if (j < 320) {                                                     \
            int kk = j >> 4, nv = j & 15;                                  \
            st4(&Bs[kk * 64 + nv * 4], pb[s]);                             \
        }                                                                  \
    }

#define GEMM_COMPUTE_STAGE                                                 \
    _Pragma("unroll")                                                      \
    for (int kk = 0; kk < 20; kk++) {                                      \
        const ulonglong2* Ap =                                             \
            reinterpret_cast<const ulonglong2*>(&As[kk * 256 + ty * 16]);  \
        const ulonglong2* Bp =                                             \
            reinterpret_cast<const ulonglong2*>(&Bs[kk * 64 + tx * 8]);    \
        ulonglong2 A0 = Ap[0], A1 = Ap[1], A2 = Ap[2], A3 = Ap[3];         \
        ulonglong2 B0 = Bp[0], B1 = Bp[1];                                 \
        ull a2[8] = {A0.x, A0.y, A1.x, A1.y, A2.x, A2.y, A3.x, A3.y};      \
        ull b2[4] = {B0.x, B0.y, B1.x, B1.y};                              \
        _Pragma("unroll")                                                  \
        for (int i = 0; i < 8; i++)                                        \
            _Pragma("unroll")                                              \
            for (int j = 0; j < 4; j++)                                    \
                acc[i][j] = fma2(a2[i], b2[j], acc[i][j]);                 \
    }

// ---------------- init GEMM: h0 = relu([x[row]|edge_attr] @ W_init + b) ----
__global__ __launch_bounds__(128, 3) void k_init(
    const float* __restrict__ x, const float* __restrict__ ea,
    const int* __restrict__ rowi,
    const float* __restrict__ W, const float* __restrict__ bias)
{
    GEMM_DECLS
    int m0 = blockIdx.y * 128;
    int n0 = blockIdx.x * 64;
    int eg = m0 + tid;
    int xbase = rowi[eg] * FNODE;
    const int NK = 4;  // K = 80

#define LOAD_STAGE(K0)                                                     \
    {                                                                      \
        int k0 = (K0);                                                     \
        _Pragma("unroll")                                                  \
        for (int v = 0; v < 5; v++) {                                      \
            int k = k0 + v * 4;                                            \
            pa[v] = (k < FNODE) ? ld4(x + xbase + k)                       \
                                : ld4(ea + eg * FEDGE + (k - FNODE));      \
        }                                                                  \
        _Pragma("unroll")                                                  \
        for (int s = 0; s < 3; s++) {                                      \
            int j = tid + s * 128;                                         \
            if (j < 320) {                                                 \
                int kk = j >> 4, nv = j & 15;                              \
                int n = n0 + nv * 4;                                       \
                pb[s] = (n < HIDN) ? ld4(W + (k0 + kk) * HIDN + n)         \
                                   : make_float4(0.f, 0.f, 0.f, 0.f);      \
            }                                                              \
        }                                                                  \
    }

    LOAD_STAGE(0)
    for (int ks = 0; ks < NK; ++ks) {
        __syncthreads();
        GEMM_STORE_STAGE
        __syncthreads();
        if (ks + 1 < NK) LOAD_STAGE((ks + 1) * 20)
        GEMM_COMPUTE_STAGE
    }
    int nb = n0 + tx * 8;
    float4 bias0 = (nb < HIDN) ? ld4(bias + nb) : make_float4(0, 0, 0, 0);
    float4 bias1 = (nb + 4 < HIDN) ? ld4(bias + nb + 4) : make_float4(0, 0, 0, 0);
#pragma unroll
    for (int i = 0; i < 8; i++) {
        int m = m0 + ty * 8 + i;
        float c0, c1, c2, c3, c4, c5, c6, c7;
        unpack2(acc[i][0], c0, c1); unpack2(acc[i][1], c2, c3);
        unpack2(acc[i][2], c4, c5); unpack2(acc[i][3], c6, c7);
        if (nb < HIDN)
            st4(g_h0 + m * HIDN + nb, make_float4(
                frelu(c0 + bias0.x), frelu(c1 + bias0.y),
                frelu(c2 + bias0.z), frelu(c3 + bias0.w)));
        if (nb + 4 < HIDN)
            st4(g_h0 + m * HIDN + nb + 4, make_float4(
                frelu(c4 + bias1.x), frelu(c5 + bias1.y),
                frelu(c6 + bias1.z), frelu(c7 + bias1.w)));
    }
#undef LOAD_STAGE
}

// ---------------- conv GEMM: h_out = relu((a[row]-h[e^1]) @ W + b + h0) ----
__global__ __launch_bounds__(128, 3) void k_conv(
    int in_sel, int out_sel,
    const int* __restrict__ rowi,
    const float* __restrict__ W, const float* __restrict__ bias)
{
    const float* h_in  = hbuf(in_sel);
    float*       h_out = hbuf(out_sel);
    GEMM_DECLS
    int m0 = blockIdx.y * 128;
    int n0 = blockIdx.x * 64;
    int eg = m0 + tid;
    int abase = rowi[eg] * HIDN;
    int hbase = (eg ^ 1) * HIDN;
    const int NK = 15;  // K = 300

#define LOAD_STAGE(K0)                                                     \
    {                                                                      \
        int k0 = (K0);                                                     \
        _Pragma("unroll")                                                  \
        for (int v = 0; v < 5; v++) {                                      \
            int k = k0 + v * 4;                                            \
            float4 a4 = ld4(g_a + abase + k);                              \
            float4 h4 = ld4(h_in + hbase + k);                             \
            pa[v] = make_float4(a4.x - h4.x, a4.y - h4.y,                  \
                                a4.z - h4.z, a4.w - h4.w);                 \
        }                                                                  \
        _Pragma("unroll")                                                  \
        for (int s = 0; s < 3; s++) {                                      \
            int j = tid + s * 128;                                         \
            if (j < 320) {                                                 \
                int kk = j >> 4, nv = j & 15;                              \
                int n = n0 + nv * 4;                                       \
                pb[s] = (n < HIDN) ? ld4(W + (k0 + kk) * HIDN + n)         \
                                   : make_float4(0.f, 0.f, 0.f, 0.f);      \
            }                                                              \
        }                                                                  \
    }

    LOAD_STAGE(0)
    for (int ks = 0; ks < NK; ++ks) {
        __syncthreads();
        GEMM_STORE_STAGE
        __syncthreads();
        if (ks + 1 < NK) LOAD_STAGE((ks + 1) * 20)
        GEMM_COMPUTE_STAGE
    }
    int nb = n0 + tx * 8;
    float4 bias0 = (nb < HIDN) ? ld4(bias + nb) : make_float4(0, 0, 0, 0);
    float4 bias1 = (nb + 4 < HIDN) ? ld4(bias + nb + 4) : make_float4(0, 0, 0, 0);
#pragma unroll
    for (int i = 0; i < 8; i++) {
        int m = m0 + ty * 8 + i;
        float c0, c1, c2, c3, c4, c5, c6, c7;
        unpack2(acc[i][0], c0, c1); unpack2(acc[i][1], c2, c3);
        unpack2(acc[i][2], c4, c5); unpack2(acc[i][3], c6, c7);
        if (nb < HIDN) {
            float4 h0v = ld4(g_h0 + m * HIDN + nb);
            st4(h_out + m * HIDN + nb, make_float4(
                frelu(c0 + bias0.x + h0v.x), frelu(c1 + bias0.y + h0v.y),
                frelu(c2 + bias0.z + h0v.z), frelu(c3 + bias0.w + h0v.w)));
        }
        if (nb + 4 < HIDN) {
            float4 h0v = ld4(g_h0 + m * HIDN + nb + 4);
            st4(h_out + m * HIDN + nb + 4, make_float4(
                frelu(c4 + bias1.x + h0v.x), frelu(c5 + bias1.y + h0v.y),
                frelu(c6 + bias1.z + h0v.z), frelu(c7 + bias1.w + h0v.w)));
        }
    }
#undef LOAD_STAGE
}

// ---------------- node GEMM: hn = relu([x|s] @ W_e2n + b); pooled += hn ----
__global__ __launch_bounds__(128, 3) void k_node(
    const float* __restrict__ x, const int* __restrict__ batch,
    const float* __restrict__ W, const float* __restrict__ bias)
{
    GEMM_DECLS
    int m0 = blockIdx.y * 128;
    int n0 = blockIdx.x * 64;
    int eg = m0 + tid;
    bool mok = (eg < NNODES);
    int safe = mok ? eg : 0;
    int xbase = safe * FNODE;
    int sbase = safe * HIDN;
    const int KTOT = FNODE + HIDN;  // 364
    const int NK = 19;

#define LOAD_STAGE(K0)                                                     \
    {                                                                      \
        int k0 = (K0);                                                     \
        _Pragma("unroll")                                                  \
        for (int v = 0; v < 5; v++) {                                      \
            int k = k0 + v * 4;                                            \
            if (k < KTOT)                                                  \
                pa[v] = (k < FNODE) ? ld4(x + xbase + k)                   \
                                    : ld4(g_a + sbase + (k - FNODE));      \
            else                                                           \
                pa[v] = make_float4(0.f, 0.f, 0.f, 0.f);                   \
        }                                                                  \
        _Pragma("unroll")                                                  \
        for (int s = 0; s < 3; s++) {                                      \
            int j = tid + s * 128;                                         \
            if (j < 320) {                                                 \
                int kk = j >> 4, nv = j & 15;                              \
                int k = k0 + kk;                                           \
                int n = n0 + nv * 4;                                       \
                pb[s] = (k < KTOT && n < HIDN)                             \
                            ? ld4(W + k * HIDN + n)                        \
                            : make_float4(0.f, 0.f, 0.f, 0.f);             \
            }                                                              \
        }                                                                  \
    }

    LOAD_STAGE(0)
    for (int ks = 0; ks < NK; ++ks) {
        __syncthreads();
        GEMM_STORE_STAGE
        __syncthreads();
        if (ks + 1 < NK) LOAD_STAGE((ks + 1) * 20)
        GEMM_COMPUTE_STAGE
    }
    int nb = n0 + tx * 8;
    float4 bias0 = (nb < HIDN) ? ld4(bias + nb) : make_float4(0, 0, 0, 0);
    float4 bias1 = (nb + 4 < HIDN) ? ld4(bias + nb + 4) : make_float4(0, 0, 0, 0);
#pragma unroll
    for (int i = 0; i < 8; i++) {
        int m = m0 + ty * 8 + i;
        if (m >= NNODES) continue;
        float c0, c1, c2, c3, c4, c5, c6, c7;
        unpack2(acc[i][0], c0, c1); unpack2(acc[i][1], c2, c3);
        unpack2(acc[i][2], c4, c5); unpack2(acc[i][3], c6, c7);
        int bg = batch[m];
        float* p = g_pool + bg * HIDN;
        if (nb < HIDN) {
            atomicAdd(p + nb + 0, frelu(c0 + bias0.x));
            atomicAdd(p + nb + 1, frelu(c1 + bias0.y));
            atomicAdd(p + nb + 2, frelu(c2 + bias0.z));
            atomicAdd(p + nb + 3, frelu(c3 + bias0.w));
        }
        if (nb + 4 < HIDN) {
            atomicAdd(p + nb + 4, frelu(c4 + bias1.x));
            atomicAdd(p + nb + 5, frelu(c5 + bias1.y));
            atomicAdd(p + nb + 6, frelu(c6 + bias1.z));
            atomicAdd(p + nb + 7, frelu(c7 + bias1.w));
        }
    }
#undef LOAD_STAGE
}

// ---------------- FFN ----------------
__global__ void k_ffn(const float* __restrict__ Wf, const float* __restrict__ bf,
                      float* __restrict__ out) {
    int g = blockIdx.x;
    int lane = threadIdx.x;
    float s = 0.f;
    for (int k = lane; k < HIDN; k += 32) s += g_pool[g * HIDN + k] * Wf[k];
#pragma unroll
    for (int o = 16; o; o >>= 1) s += __shfl_xor_sync(0xffffffffu, s, o);
    if (lane == 0) out[g] = s + bf[0];
}

// ---------------- entry ----------------
extern "C" void kernel_launch(void* const* d_in, const int* in_sizes, int n_in,
                              void* d_out, int out_size) {
    const float* x     = (const float*)d_in[0];
    const float* ea    = (const float*)d_in[1];
    const int*   ei    = (const int*)d_in[2];
    const int*   rowi  = ei;
    const int*   coli  = ei + NEDGES;
    const int*   batch = (const int*)d_in[3];
    const float* Wi    = (const float*)d_in[4];
    const float* bi    = (const float*)d_in[5];
    const float* Wc    = (const float*)d_in[6];
    const float* bc    = (const float*)d_in[7];
    const float* We    = (const float*)d_in[8];
    const float* be    = (const float*)d_in[9];
    const float* Wf    = (const float*)d_in[10];
    const float* bf    = (const float*)d_in[11];
    float* out = (float*)d_out;

    dim3 gE(5, NEDGES / 128);               // 5 x 2500
    dim3 gN(5, (NNODES + 127) / 128);       // 5 x 157

    // Launch order keeps a heavy GEMM (k_init) at the position the ncu
    // window profiles, so next round shows GEMM data instead of k_scatter.
    k_zero<<<(NGRAPH * HIDN + 255) / 256, 256>>>();          // 1
    k_hist<<<NEDGES / 256, 256>>>(coli);                     // 2
    k_scan<<<1, 1024>>>();                                   // 3
    k_init<<<gE, 128>>>(x, ea, rowi, Wi, bi);                // 4  <- profiled
    k_scatter<<<NEDGES / 256, 256>>>(coli);                  // 5

    int cur = 0;  // g_h0
    for (int l = 0; l < 3; ++l) {
        k_segsum<<<(NNODES * 75 + 255) / 256, 256>>>(cur);
        int nxt = (cur == 1) ? 2 : 1;
        k_conv<<<gE, 128>>>(cur, nxt, rowi, Wc + l * HIDN * HIDN, bc + l * HIDN);
        cur = nxt;
    }

    k_segsum<<<(NNODES * 75 + 255) / 256, 256>>>(cur);
    k_node<<<gN, 128>>>(x, batch, We, be);
    k_ffn<<<NGRAPH, 32>>>(Wf, bf, out);
}

// round 4
// speedup vs baseline: 2.3886x; 1.8462x over previous
#include <cuda_runtime.h>
#include <cuda_bf16.h>
#include <cstdint>

#define NNODES 20000
#define NEDGES 320000
#define FNODE  64
#define FEDGE  16
#define HIDN   300
#define NGRAPH 128

typedef unsigned long long ull;

// ---------------- scratch (device globals: allocation-free rule) -------------
__device__ float g_h0[NEDGES * HIDN];
__device__ float g_hA[NEDGES * HIDN];
__device__ float g_hB[NEDGES * HIDN];
__device__ float g_a [NNODES * HIDN];   // u_l = segsum(t_l)
__device__ float g_s [NNODES * HIDN];   // final node message s
__device__ float g_pool[NGRAPH * HIDN];
__device__ __nv_bfloat16 g_Wh[3 * 320 * 320];   // W^T hi, [layer][n][k], zero-padded
__device__ __nv_bfloat16 g_Wl[3 * 320 * 320];   // W^T lo
__device__ int   g_cnt [NNODES];
__device__ int   g_ptr [NNODES + 1];
__device__ int   g_fill[NNODES];
__device__ int   g_eid [NEDGES];

__device__ __forceinline__ float* hbuf(int s) {
    return (s == 0) ? g_h0 : ((s == 1) ? g_hA : g_hB);
}

// ---------------- small helpers ----------------
__device__ __forceinline__ float4 ld4(const float* p) { return *reinterpret_cast<const float4*>(p); }
__device__ __forceinline__ void   st4(float* p, float4 v) { *reinterpret_cast<float4*>(p) = v; }
__device__ __forceinline__ float  frelu(float x) { return x > 0.f ? x : 0.f; }

__device__ __forceinline__ ull fma2(ull a, ull b, ull c) {
    ull d;
    asm("fma.rn.f32x2 %0, %1, %2, %3;" : "=l"(d) : "l"(a), "l"(b), "l"(c));
    return d;
}
__device__ __forceinline__ void unpack2(ull v, float& lo, float& hi) {
    asm("mov.b64 {%0, %1}, %2;" : "=f"(lo), "=f"(hi) : "l"(v));
}

__device__ __forceinline__ uint32_t smem_u32(const void* p) {
    uint32_t a;
    asm("{ .reg .u64 t; cvta.to.shared.u64 t, %1; cvt.u32.u64 %0, t; }" : "=r"(a) : "l"(p));
    return a;
}
__device__ __forceinline__ uint32_t sw128(uint32_t o) { return o ^ ((o >> 3) & 0x70); }

// mma.sync / ldmatrix (baseline PTX, valid on plain sm_103)
__device__ __forceinline__ void ldsm4(uint32_t* r, uint32_t a) {
    asm volatile("ldmatrix.sync.aligned.m8n8.x4.shared.b16 {%0,%1,%2,%3}, [%4];"
                 : "=r"(r[0]), "=r"(r[1]), "=r"(r[2]), "=r"(r[3]) : "r"(a));
}
__device__ __forceinline__ void mma_bf(float* d, const uint32_t* a, const uint32_t* b) {
    asm volatile("mma.sync.aligned.m16n8k16.row.col.f32.bf16.bf16.f32 "
                 "{%0,%1,%2,%3}, {%4,%5,%6,%7}, {%8,%9}, {%0,%1,%2,%3};"
                 : "+f"(d[0]), "+f"(d[1]), "+f"(d[2]), "+f"(d[3])
                 : "r"(a[0]), "r"(a[1]), "r"(a[2]), "r"(a[3]), "r"(b[0]), "r"(b[1]));
}

// ---------------- preprocessing: zero + W transpose/split ----------------
__global__ void k_pre(const float* __restrict__ Wc) {
    int t = blockIdx.x * blockDim.x + threadIdx.x;
    if (t < NNODES) g_cnt[t] = 0;
    if (t < NGRAPH * HIDN) g_pool[t] = 0.f;
    if (t < 3 * 102400) {
        int r2 = t % 102400;
        int l  = t / 102400;
        int n = r2 / 320, k = r2 % 320;
        float v = (n < HIDN && k < HIDN) ? Wc[l * HIDN * HIDN + k * HIDN + n] : 0.f;
        __nv_bfloat16 bh = __float2bfloat16(v);
        float lo = v - __bfloat162float(bh);
        g_Wh[t] = bh;
        g_Wl[t] = __float2bfloat16(lo);
    }
}

__global__ void k_hist(const int* __restrict__ coli) {
    int e = blockIdx.x * blockDim.x + threadIdx.x;
    if (e < NEDGES) atomicAdd(&g_cnt[coli[e]], 1);
}

__global__ void k_scan() {
    __shared__ int sh[1024];
    int tid = threadIdx.x;
    int carry = 0;
    const int CH = (NNODES + 1023) / 1024;
    for (int c = 0; c < CH; ++c) {
        int i = c * 1024 + tid;
        int v = (i < NNODES) ? g_cnt[i] : 0;
        sh[tid] = v;
        __syncthreads();
        for (int off = 1; off < 1024; off <<= 1) {
            int t = (tid >= off) ? sh[tid - off] : 0;
            __syncthreads();
            sh[tid] += t;
            __syncthreads();
        }
        int inc = sh[tid];
        int total = sh[1023];
        if (i < NNODES) {
            int ex = carry + inc - v;
            g_ptr[i]  = ex;
            g_fill[i] = ex;
        }
        carry += total;
        __syncthreads();
    }
    if (tid == 0) g_ptr[NNODES] = carry;
}

__global__ void k_scatter(const int* __restrict__ coli) {
    int e = blockIdx.x * blockDim.x + threadIdx.x;
    if (e < NEDGES) {
        int pos = atomicAdd(&g_fill[coli[e]], 1);
        g_eid[pos] = e;
    }
}

// ---------------- segment sum: dst[n] = sum_{e: col[e]==n} src[e] -------------
__global__ void k_segsum(int src_sel, int dst_sel) {
    const float* h = hbuf(src_sel);
    float* dst = dst_sel ? g_s : g_a;
    int t = blockIdx.x * blockDim.x + threadIdx.x;
    if (t >= NNODES * 75) return;
    int n = t / 75;
    int c = (t - n * 75) * 4;
    int beg = g_ptr[n], end = g_ptr[n + 1];
    float4 acc = make_float4(0.f, 0.f, 0.f, 0.f);
    for (int i = beg; i < end; ++i) {
        int e = g_eid[i];
        float4 vv = ld4(h + e * HIDN + c);
        acc.x += vv.x; acc.y += vv.y; acc.z += vv.z; acc.w += vv.w;
    }
    st4(dst + n * HIDN + c, acc);
}

// =====================================================================
// Tensor GEMM via mma.sync: t_out = h_layer @ W_layer
// CTA tile 128m x 160n, 8 warps (4m x 2n), warp tile 32 x 80.
// K chunks of 64 in smem (A hi/lo + B hi/lo, SW128), 3-pass bf16 split.
// h_layer assembled on the fly:
//   layer 0: h0 ; layer>=1: relu(h0 + bc + u[row[e]] - t_prev[e^1])
// =====================================================================
#define TG_A_HI 0
#define TG_A_LO 16384
#define TG_B_HI 32768
#define TG_B_LO 53248
#define TG_TOTAL 73728

__global__ void __launch_bounds__(256) k_tgemm(
    int layer, int prev_sel, int out_sel,
    const int* __restrict__ rowi, const float* __restrict__ bc)
{
    extern __shared__ char smem[];
    uint32_t sb = smem_u32(smem);
    int tid = threadIdx.x;
    int lane = tid & 31;
    int wid = tid >> 5;
    int m0 = blockIdx.y * 128;
    int n0 = blockIdx.x * 160;

    const float* tprev = hbuf(prev_sel);
    float* tout = hbuf(out_sel);

    // A-assembly mapping: thread -> (row r, 32-col half)
    int r   = tid >> 1;
    int e   = m0 + r;
    int cc0 = (tid & 1) * 32;
    int rv  = (layer > 0) ? rowi[e] : 0;

    // warp tile / ldmatrix lane mapping
    int wm = wid >> 1, wn = wid & 1;
    int mat = lane >> 3, l7 = lane & 7;
    int a_row = wm * 32 + (mat & 1) * 8 + l7;     // + mt*16
    int a_kof = (mat >> 1) * 8;
    int b_row = wn * 80 + (mat >> 1) * 8 + l7;    // + np*16
    int b_kof = (mat & 1) * 8;

    float acc[2][10][4];
#pragma unroll
    for (int i = 0; i < 2; i++)
#pragma unroll
        for (int j = 0; j < 10; j++)
#pragma unroll
            for (int q = 0; q < 4; q++) acc[i][j][q] = 0.f;

    for (int kc = 0; kc < 5; ++kc) {
        int k0 = kc * 64;
        __syncthreads();

        // ---- B chunk: 160 n-rows x 64 k (hi & lo) ----
        {
            const __nv_bfloat16* wh = g_Wh + layer * 102400 + (n0 + 0) * 320 + k0;
            const __nv_bfloat16* wl = g_Wl + layer * 102400 + (n0 + 0) * 320 + k0;
#pragma unroll
            for (int s = 0; s < 5; s++) {
                int j = tid + s * 256;          // j < 1280
                int n = j >> 3, i = j & 7;
                uint4 vh = *(reinterpret_cast<const uint4*>(wh + n * 320) + i);
                uint4 vl = *(reinterpret_cast<const uint4*>(wl + n * 320) + i);
                uint32_t off = sw128((uint32_t)(n * 128 + i * 16));
                *reinterpret_cast<uint4*>(smem + TG_B_HI + off) = vh;
                *reinterpret_cast<uint4*>(smem + TG_B_LO + off) = vl;
            }
        }
        // ---- A chunk: assemble 128 rows x 64 k -> bf16 hi/lo ----
#pragma unroll
        for (int i = 0; i < 8; i++) {
            int cc = cc0 + i * 4;
            int k = k0 + cc;
            float4 v = make_float4(0.f, 0.f, 0.f, 0.f);
            if (k < HIDN) {
                if (layer == 0) {
                    v = ld4(g_h0 + e * HIDN + k);
                } else {
                    float4 h0v = ld4(g_h0 + e * HIDN + k);
                    float4 uv  = ld4(g_a + rv * HIDN + k);
                    float4 tv  = ld4(tprev + (e ^ 1) * HIDN + k);
                    float4 bv  = ld4(bc + k);
                    v.x = frelu(h0v.x + bv.x + uv.x - tv.x);
                    v.y = frelu(h0v.y + bv.y + uv.y - tv.y);
                    v.z = frelu(h0v.z + bv.z + uv.z - tv.z);
                    v.w = frelu(h0v.w + bv.w + uv.w - tv.w);
                }
            }
            __nv_bfloat16 bx = __float2bfloat16(v.x), by = __float2bfloat16(v.y);
            __nv_bfloat16 bz = __float2bfloat16(v.z), bw = __float2bfloat16(v.w);
            __nv_bfloat162 h0p, h1p, l0p, l1p;
            h0p.x = bx; h0p.y = by; h1p.x = bz; h1p.y = bw;
            l0p.x = __float2bfloat16(v.x - __bfloat162float(bx));
            l0p.y = __float2bfloat16(v.y - __bfloat162float(by));
            l1p.x = __float2bfloat16(v.z - __bfloat162float(bz));
            l1p.y = __float2bfloat16(v.w - __bfloat162float(bw));
            uint32_t off = sw128((uint32_t)(r * 128 + cc * 2));
            *reinterpret_cast<uint32_t*>(smem + TG_A_HI + off)     = *reinterpret_cast<uint32_t*>(&h0p);
            *reinterpret_cast<uint32_t*>(smem + TG_A_HI + off + 4) = *reinterpret_cast<uint32_t*>(&h1p);
            *reinterpret_cast<uint32_t*>(smem + TG_A_LO + off)     = *reinterpret_cast<uint32_t*>(&l0p);
            *reinterpret_cast<uint32_t*>(smem + TG_A_LO + off + 4) = *reinterpret_cast<uint32_t*>(&l1p);
        }
        __syncthreads();

        // ---- compute: 4 k16 steps x (A frags + 5 n-pair tiles) ----
#pragma unroll
        for (int ks = 0; ks < 4; ++ks) {
            uint32_t ah[2][4], al[2][4];
#pragma unroll
            for (int mt = 0; mt < 2; ++mt) {
                uint32_t off = sw128((uint32_t)(((a_row + mt * 16) << 7) +
                                                ((ks * 16 + a_kof) << 1)));
                ldsm4(ah[mt], sb + TG_A_HI + off);
                ldsm4(al[mt], sb + TG_A_LO + off);
            }
#pragma unroll
            for (int np = 0; np < 5; ++np) {
                uint32_t boff = sw128((uint32_t)(((b_row + np * 16) << 7) +
                                                 ((ks * 16 + b_kof) << 1)));
                uint32_t bh[4], bl[4];
                ldsm4(bh, sb + TG_B_HI + boff);
                ldsm4(bl, sb + TG_B_LO + boff);
#pragma unroll
                for (int mt = 0; mt < 2; ++mt)
#pragma unroll
                    for (int h = 0; h < 2; ++h) {
                        float* d = acc[mt][np * 2 + h];
                        mma_bf(d, ah[mt], bh + h * 2);
                        mma_bf(d, ah[mt], bl + h * 2);
                        mma_bf(d, al[mt], bh + h * 2);
                    }
            }
        }
    }

    // ---- epilogue: fragments -> fp32 t ----
    int orow = m0 + wm * 32 + (lane >> 2);
    int ocol = n0 + wn * 80 + (lane & 3) * 2;
#pragma unroll
    for (int mt = 0; mt < 2; ++mt)
#pragma unroll
        for (int nt = 0; nt < 10; ++nt) {
            int col = ocol + nt * 8;
            if (col >= HIDN) continue;
#pragma unroll
            for (int h = 0; h < 2; ++h) {
                int row = orow + mt * 16 + h * 8;
                float2 vv = make_float2(acc[mt][nt][h * 2], acc[mt][nt][h * 2 + 1]);
                *reinterpret_cast<float2*>(tout + row * HIDN + col) = vv;
            }
        }
}

// ---------------- h3 materialize: g_hB = relu(h0 + bc2 + u2[row] - rev(t2)) --
__global__ void k_h3(int prev_sel, const float* __restrict__ bc2,
                     const int* __restrict__ rowi) {
    int t = blockIdx.x * blockDim.x + threadIdx.x;
    if (t >= NEDGES * 75) return;
    int e = t / 75;
    int c = (t - e * 75) * 4;
    const float* t2 = hbuf(prev_sel);
    float4 h0v = ld4(g_h0 + e * HIDN + c);
    float4 uv  = ld4(g_a + rowi[e] * HIDN + c);
    float4 tv  = ld4(t2 + (e ^ 1) * HIDN + c);
    float4 bv  = ld4(bc2 + c);
    st4(g_hB + e * HIDN + c, make_float4(
        frelu(h0v.x + bv.x + uv.x - tv.x), frelu(h0v.y + bv.y + uv.y - tv.y),
        frelu(h0v.z + bv.z + uv.z - tv.z), frelu(h0v.w + bv.w + uv.w - tv.w)));
}

// =====================================================================
// FFMA2 GEMM core (k_init / k_node): 128x64 tile, 8x8/thread
// =====================================================================
#define GEMM_DECLS                                                         \
    __shared__ __align__(16) float As[20 * 256];                           \
    __shared__ __align__(16) float Bs[20 * 64];                            \
    float2* As2 = reinterpret_cast<float2*>(As);                           \
    int tid = threadIdx.x;                                                 \
    int ty = tid >> 3, tx = tid & 7;                                       \
    ull acc[8][4];                                                         \
    _Pragma("unroll")                                                      \
    for (int i = 0; i < 8; i++)                                            \
        _Pragma("unroll")                                                  \
        for (int j = 0; j < 4; j++) acc[i][j] = 0ull;                      \
    float4 pa[5], pb[3];

#define GEMM_STORE_STAGE                                                   \
    _Pragma("unroll")                                                      \
    for (int v = 0; v < 5; v++) {                                          \
        float4 w = pa[v];                                                  \
        As2[(v * 4 + 0) * 128 + tid] = make_float2(w.x, w.x);              \
        As2[(v * 4 + 1) * 128 + tid] = make_float2(w.y, w.y);              \
        As2[(v * 4 + 2) * 128 + tid] = make_float2(w.z, w.z);              \
        As2[(v * 4 + 3) * 128 + tid] = make_float2(w.w, w.w);              \
    }                                                                      \
    _Pragma("unroll")                                                      \
    for (int s = 0; s < 3; s++) {                                          \
        int j = tid + s * 128;                                             \
        if (j < 320) {                                                     \
            int kk = j >> 4, nv = j & 15;                                  \
            st4(&Bs[kk * 64 + nv * 4], pb[s]);                             \
        }                                                                  \
    }

#define GEMM_COMPUTE_STAGE                                                 \
    _Pragma("unroll")                                                      \
    for (int kk = 0; kk < 20; kk++) {                                      \
        const ulonglong2* Ap =                                             \
            reinterpret_cast<const ulonglong2*>(&As[kk * 256 + ty * 16]);  \
        const ulonglong2* Bp =                                             \
            reinterpret_cast<const ulonglong2*>(&Bs[kk * 64 + tx * 8]);    \
        ulonglong2 A0 = Ap[0], A1 = Ap[1], A2 = Ap[2], A3 = Ap[3];         \
        ulonglong2 B0 = Bp[0], B1 = Bp[1];                                 \
        ull a2[8] = {A0.x, A0.y, A1.x, A1.y, A2.x, A2.y, A3.x, A3.y};      \
        ull b2[4] = {B0.x, B0.y, B1.x, B1.y};                              \
        _Pragma("unroll")                                                  \
        for (int i = 0; i < 8; i++)                                        \
            _Pragma("unroll")                                              \
            for (int j = 0; j < 4; j++)                                    \
                acc[i][j] = fma2(a2[i], b2[j], acc[i][j]);                 \
    }

// ---------------- init GEMM: h0 = relu([x[row]|edge_attr] @ W_init + b) ----
__global__ __launch_bounds__(128, 3) void k_init(
    const float* __restrict__ x, const float* __restrict__ ea,
    const int* __restrict__ rowi,
    const float* __restrict__ W, const float* __restrict__ bias)
{
    GEMM_DECLS
    int m0 = blockIdx.y * 128;
    int n0 = blockIdx.x * 64;
    int eg = m0 + tid;
    int xbase = rowi[eg] * FNODE;
    const int NK = 4;  // K = 80

#define LOAD_STAGE(K0)                                                     \
    {                                                                      \
        int k0 = (K0);                                                     \
        _Pragma("unroll")                                                  \
        for (int v = 0; v < 5; v++) {                                      \
            int k = k0 + v * 4;                                            \
            pa[v] = (k < FNODE) ? ld4(x + xbase + k)                       \
                                : ld4(ea + eg * FEDGE + (k - FNODE));      \
        }                                                                  \
        _Pragma("unroll")                                                  \
        for (int s = 0; s < 3; s++) {                                      \
            int j = tid + s * 128;                                         \
            if (j < 320) {                                                 \
                int kk = j >> 4, nv = j & 15;                              \
                int n = n0 + nv * 4;                                       \
                pb[s] = (n < HIDN) ? ld4(W + (k0 + kk) * HIDN + n)         \
                                   : make_float4(0.f, 0.f, 0.f, 0.f);      \
            }                                                              \
        }                                                                  \
    }

    LOAD_STAGE(0)
    for (int ks = 0; ks < NK; ++ks) {
        __syncthreads();
        GEMM_STORE_STAGE
        __syncthreads();
        if (ks + 1 < NK) LOAD_STAGE((ks + 1) * 20)
        GEMM_COMPUTE_STAGE
    }
    int nb = n0 + tx * 8;
    float4 bias0 = (nb < HIDN) ? ld4(bias + nb) : make_float4(0, 0, 0, 0);
    float4 bias1 = (nb + 4 < HIDN) ? ld4(bias + nb + 4) : make_float4(0, 0, 0, 0);
#pragma unroll
    for (int i = 0; i < 8; i++) {
        int m = m0 + ty * 8 + i;
        float c0, c1, c2, c3, c4, c5, c6, c7;
        unpack2(acc[i][0], c0, c1); unpack2(acc[i][1], c2, c3);
        unpack2(acc[i][2], c4, c5); unpack2(acc[i][3], c6, c7);
        if (nb < HIDN)
            st4(g_h0 + m * HIDN + nb, make_float4(
                frelu(c0 + bias0.x), frelu(c1 + bias0.y),
                frelu(c2 + bias0.z), frelu(c3 + bias0.w)));
        if (nb + 4 < HIDN)
            st4(g_h0 + m * HIDN + nb + 4, make_float4(
                frelu(c4 + bias1.x), frelu(c5 + bias1.y),
                frelu(c6 + bias1.z), frelu(c7 + bias1.w)));
    }
#undef LOAD_STAGE
}

// ---------------- node GEMM: hn = relu([x|s] @ W_e2n + b); pooled += hn ----
__global__ __launch_bounds__(128, 3) void k_node(
    const float* __restrict__ x, const int* __restrict__ batch,
    const float* __restrict__ W, const float* __restrict__ bias)
{
    GEMM_DECLS
    int m0 = blockIdx.y * 128;
    int n0 = blockIdx.x * 64;
    int eg = m0 + tid;
    bool mok = (eg < NNODES);
    int safe = mok ? eg : 0;
    int xbase = safe * FNODE;
    int sbase = safe * HIDN;
    const int KTOT = FNODE + HIDN;  // 364
    const int NK = 19;

#define LOAD_STAGE(K0)                                                     \
    {                                                                      \
        int k0 = (K0);                                                     \
        _Pragma("unroll")                                                  \
        for (int v = 0; v < 5; v++) {                                      \
            int k = k0 + v * 4;                                            \
            if (k < KTOT)                                                  \
                pa[v] = (k < FNODE) ? ld4(x + xbase + k)                   \
                                    : ld4(g_s + sbase + (k - FNODE));      \
            else                                                           \
                pa[v] = make_float4(0.f, 0.f, 0.f, 0.f);                   \
        }                                                                  \
        _Pragma("unroll")                                                  \
        for (int s = 0; s < 3; s++) {                                      \
            int j = tid + s * 128;                                         \
            if (j < 320) {                                                 \
                int kk = j >> 4, nv = j & 15;                              \
                int k = k0 + kk;                                           \
                int n = n0 + nv * 4;                                       \
                pb[s] = (k < KTOT && n < HIDN)                             \
                            ? ld4(W + k * HIDN + n)                        \
                            : make_float4(0.f, 0.f, 0.f, 0.f);             \
            }                                                              \
        }                                                                  \
    }

    LOAD_STAGE(0)
    for (int ks = 0; ks < NK; ++ks) {
        __syncthreads();
        GEMM_STORE_STAGE
        __syncthreads();
        if (ks + 1 < NK) LOAD_STAGE((ks + 1) * 20)
        GEMM_COMPUTE_STAGE
    }
    int nb = n0 + tx * 8;
    float4 bias0 = (nb < HIDN) ? ld4(bias + nb) : make_float4(0, 0, 0, 0);
    float4 bias1 = (nb + 4 < HIDN) ? ld4(bias + nb + 4) : make_float4(0, 0, 0, 0);
#pragma unroll
    for (int i = 0; i < 8; i++) {
        int m = m0 + ty * 8 + i;
        if (m >= NNODES) continue;
        float c0, c1, c2, c3, c4, c5, c6, c7;
        unpack2(acc[i][0], c0, c1); unpack2(acc[i][1], c2, c3);
        unpack2(acc[i][2], c4, c5); unpack2(acc[i][3], c6, c7);
        int bg = batch[m];
        float* p = g_pool + bg * HIDN;
        if (nb < HIDN) {
            atomicAdd(p + nb + 0, frelu(c0 + bias0.x));
            atomicAdd(p + nb + 1, frelu(c1 + bias0.y));
            atomicAdd(p + nb + 2, frelu(c2 + bias0.z));
            atomicAdd(p + nb + 3, frelu(c3 + bias0.w));
        }
        if (nb + 4 < HIDN) {
            atomicAdd(p + nb + 4, frelu(c4 + bias1.x));
            atomicAdd(p + nb + 5, frelu(c5 + bias1.y));
            atomicAdd(p + nb + 6, frelu(c6 + bias1.z));
            atomicAdd(p + nb + 7, frelu(c7 + bias1.w));
        }
    }
#undef LOAD_STAGE
}

// ---------------- FFN ----------------
__global__ void k_ffn(const float* __restrict__ Wf, const float* __restrict__ bf,
                      float* __restrict__ out) {
    int g = blockIdx.x;
    int lane = threadIdx.x;
    float s = 0.f;
    for (int k = lane; k < HIDN; k += 32) s += g_pool[g * HIDN + k] * Wf[k];
#pragma unroll
    for (int o = 16; o; o >>= 1) s += __shfl_xor_sync(0xffffffffu, s, o);
    if (lane == 0) out[g] = s + bf[0];
}

// ---------------- entry ----------------
extern "C" void kernel_launch(void* const* d_in, const int* in_sizes, int n_in,
                              void* d_out, int out_size) {
    const float* x     = (const float*)d_in[0];
    const float* ea    = (const float*)d_in[1];
    const int*   ei    = (const int*)d_in[2];
    const int*   rowi  = ei;
    const int*   coli  = ei + NEDGES;
    const int*   batch = (const int*)d_in[3];
    const float* Wi    = (const float*)d_in[4];
    const float* bi    = (const float*)d_in[5];
    const float* Wc    = (const float*)d_in[6];
    const float* bc    = (const float*)d_in[7];
    const float* We    = (const float*)d_in[8];
    const float* be    = (const float*)d_in[9];
    const float* Wf    = (const float*)d_in[10];
    const float* bf    = (const float*)d_in[11];
    float* out = (float*)d_out;

    cudaFuncSetAttribute(k_tgemm, cudaFuncAttributeMaxDynamicSharedMemorySize, TG_TOTAL);

    dim3 gE(5, NEDGES / 128);
    dim3 gT(2, NEDGES / 128);   // 2 n-blocks x 2500 m-blocks

    k_pre<<<1200, 256>>>(Wc);                                       // 1
    k_hist<<<NEDGES / 256, 256>>>(coli);                            // 2
    k_init<<<gE, 128>>>(x, ea, rowi, Wi, bi);                       // 3
    k_tgemm<<<gT, 256, TG_TOTAL>>>(0, 0, 1, rowi, bc);              // 4 <- profiled
    k_scan<<<1, 1024>>>();                                          // 5
    k_scatter<<<NEDGES / 256, 256>>>(coli);                         // 6

    k_segsum<<<(NNODES * 75 + 255) / 256, 256>>>(1, 0);             // u0 = segsum(t0)
    k_tgemm<<<gT, 256, TG_TOTAL>>>(1, 1, 2, rowi, bc);              // t1
    k_segsum<<<(NNODES * 75 + 255) / 256, 256>>>(2, 0);             // u1
    k_tgemm<<<gT, 256, TG_TOTAL>>>(2, 2, 1, rowi, bc + HIDN);       // t2
    k_segsum<<<(NNODES * 75 + 255) / 256, 256>>>(1, 0);             // u2
    k_h3<<<(NEDGES * 75 + 255) / 256, 256>>>(1, bc + 2 * HIDN, rowi);
    k_segsum<<<(NNODES * 75 + 255) / 256, 256>>>(2, 1);             // s -> g_s

    dim3 gN(5, (NNODES + 127) / 128);
    k_node<<<gN, 128>>>(x, batch, We, be);
    k_ffn<<<NGRAPH, 32>>>(Wf, bf, out);
}